// round 15
// baseline (speedup 1.0000x reference)
#include <cuda_runtime.h>
#include <cuda_fp16.h>
#include <cstdint>
#include <math.h>

#define Bz 8
#define Sz 2048
#define Dz 1024
#define Nz 256
#define Hz 512
#define Ez 8
#define Tz (Bz*Sz)   // 16384 tokens

typedef unsigned int uint;
typedef unsigned short ushort;

// ---------------- scratch (static device allocations, allowed) -------------
__device__ int   g_routes[Tz];
__device__ int   g_cnt[Ez];
__device__ int   g_off[Ez+1];
__device__ int   g_cur[Ez];
__device__ int   g_tok[Tz];

__device__ float g_u [(size_t)Tz*Nz];
__device__ float g_a [(size_t)Tz*Nz];
__device__ float g_bu[(size_t)Tz*Nz];
__device__ float g_c [(size_t)Tz*Nz];
__device__ float g_sk[(size_t)Tz*Nz];

// fp16 operand buffers (single-rounded activations AND weights)
__device__ ushort g_xh [(size_t)Tz*Dz];
__device__ ushort g_shh[(size_t)Tz*Hz];
__device__ ushort g_yh [(size_t)Tz*Nz];
__device__ ushort g_winh [(size_t)Ez*Nz*Dz];
__device__ ushort g_wsinh[(size_t)Ez*Hz*Dz];
__device__ ushort g_wsouth[(size_t)Ez*4*Nz*Hz];
__device__ ushort g_wouth[(size_t)Ez*Dz*Nz];

// ---------------- helpers ----------------------------------------------------
__device__ __forceinline__ uint32_t smem_u32(const void* p){
    uint32_t a;
    asm("{ .reg .u64 t; cvta.to.shared.u64 t, %1; cvt.u32.u64 %0, t; }" : "=r"(a) : "l"(p));
    return a;
}
__device__ __forceinline__ float tanh_fast(float x){
    float r; asm("tanh.approx.f32 %0, %1;" : "=f"(r) : "f"(x)); return r;
}
__device__ __forceinline__ float sig_fast(float x){ return fmaf(0.5f, tanh_fast(0.5f*x), 0.5f); }

// pack two floats into f16x2 (lo in low half)
__device__ __forceinline__ uint hf2(float lo, float hi){
    uint r; asm("cvt.rn.f16x2.f32 %0, %1, %2;" : "=r"(r) : "f"(hi), "f"(lo)); return r;
}
// SW64 swizzle for 64-byte SMEM rows (conflict-free ldmatrix with BK=32 fp16)
__device__ __forceinline__ uint32_t sw64(uint32_t o){ return o ^ ((o>>3)&0x30); }

#define CP16(dst, src, sz) \
    asm volatile("cp.async.cg.shared.global [%0], [%1], 16, %2;" \
                 :: "r"(dst), "l"(src), "r"(sz) : "memory")
#define CP_COMMIT() asm volatile("cp.async.commit_group;" ::: "memory")
template<int N> __device__ __forceinline__ void cp_wait(){
    asm volatile("cp.async.wait_group %0;" :: "n"(N) : "memory");
}
#define LDSM4(r, addr) \
    asm volatile("ldmatrix.sync.aligned.m8n8.x4.shared.b16 {%0,%1,%2,%3}, [%4];" \
                 : "=r"((r)[0]),"=r"((r)[1]),"=r"((r)[2]),"=r"((r)[3]) : "r"(addr))
#define MMA(d, a, b0_, b1_) \
    asm volatile("mma.sync.aligned.m16n8k16.row.col.f32.f16.f16.f32 " \
                 "{%0,%1,%2,%3},{%4,%5,%6,%7},{%8,%9},{%0,%1,%2,%3};" \
                 : "+f"((d)[0]),"+f"((d)[1]),"+f"((d)[2]),"+f"((d)[3]) \
                 : "r"((a)[0]),"r"((a)[1]),"r"((a)[2]),"r"((a)[3]), "r"(b0_),"r"(b1_))

// ---------------- fused fp32 -> fp16 conversion (ALL tensors) -----------------
__device__ __forceinline__ void cvt_h(const float4* __restrict__ s,
                                      uint2* __restrict__ dh, size_t i){
    float4 v = s[i];
    uint2 o; o.x = hf2(v.x, v.y); o.y = hf2(v.z, v.w);
    dh[i] = o;
}

__global__ void k_split_all(const float* __restrict__ x,   const float* __restrict__ Win,
                            const float* __restrict__ Wsin, const float* __restrict__ Wsout,
                            const float* __restrict__ Wout){
    constexpr size_t c0 = (size_t)Tz*Dz/4;                 // x
    constexpr size_t c1 = c0 + (size_t)Ez*Nz*Dz/4;         // + win
    constexpr size_t c2 = c1 + (size_t)Ez*Hz*Dz/4;         // + wsin
    constexpr size_t c3 = c2 + (size_t)Ez*4*Nz*Hz/4;       // + wsout
    constexpr size_t c4 = c3 + (size_t)Ez*Dz*Nz/4;         // + wout
    size_t i = (size_t)blockIdx.x*blockDim.x + threadIdx.x;
    size_t stride = (size_t)gridDim.x*blockDim.x;
    for (; i < c4; i += stride){
        if (i < c0)      cvt_h((const float4*)x,     (uint2*)g_xh,     i);
        else if (i < c1) cvt_h((const float4*)Win,   (uint2*)g_winh,   i - c0);
        else if (i < c2) cvt_h((const float4*)Wsin,  (uint2*)g_wsinh,  i - c1);
        else if (i < c3) cvt_h((const float4*)Wsout, (uint2*)g_wsouth, i - c2);
        else             cvt_h((const float4*)Wout,  (uint2*)g_wouth,  i - c3);
    }
}

// ---------------- routing / counting sort ------------------------------------
__global__ void k_zero(){
    int t = threadIdx.x;
    if (t < Ez){ g_cnt[t] = 0; g_cur[t] = 0; }
}
__global__ void k_route(const int* __restrict__ tid){
    int t = blockIdx.x*256 + threadIdx.x;
    if (t >= Tz) return;
    unsigned x = (unsigned)tid[t];
    x ^= x >> 16; x *= 2246822507u;
    x ^= x >> 13; x *= 3266489909u;
    x ^= x >> 16;
    int r = (int)(x & (unsigned)(Ez-1));
    g_routes[t] = r;
    atomicAdd(&g_cnt[r], 1);
}
__global__ void k_off(){
    int s = 0;
    for (int e = 0; e < Ez; e++){ g_off[e] = s; s += g_cnt[e]; }
    g_off[Ez] = s;
}
__global__ void k_scatter(){
    int t = blockIdx.x*256 + threadIdx.x;
    if (t >= Tz) return;
    int r = g_routes[t];
    int pos = g_off[r] + atomicAdd(&g_cur[r], 1);
    g_tok[pos] = t;
}

// ---------------- HMMA grouped GEMM ------------------------------------------
// CTA tile: 128 tokens x 128 cols, BK=32, 8 warps (4x2), warp tile 32x64.
// Single-pass fp16, fp32 accumulate. 3-stage cp.async pipeline (wait_group 1).
// Per stage: A 8K | B 8K = 16KB; 3 stages + 1K header = 50176 B; occupancy 2.
#define SM_BUF     1024
#define OFF_B      8192
#define BUF_STRIDE 16384
#define SMEM_BYTES (SM_BUF + 3*BUF_STRIDE)

template<int STAGE>
__global__ void __launch_bounds__(256,2)
k_gemm(const float* __restrict__ dpar, float* __restrict__ outp)
{
    constexpr int KD = (STAGE==0) ? Dz : (STAGE==1) ? Hz : Nz;
    constexpr int NS = KD / 32;

    const int e   = blockIdx.z;
    const int cnt = g_cnt[e];
    const int mt  = blockIdx.y;
    if (mt*128 >= cnt) return;
    const int off  = g_off[e];
    const int col0 = blockIdx.x * 128;

    const ushort* Ah = (STAGE==0) ? g_xh : (STAGE==1) ? g_shh : g_yh;
    const ushort* Wbp;
    if (STAGE==0){
        Wbp = (col0 < Nz) ? (g_winh + ((size_t)e*Nz + col0)*(size_t)KD)
                          : (g_wsinh + ((size_t)e*Hz + (col0-Nz))*(size_t)KD);
    } else if (STAGE==1){
        Wbp = g_wsouth + ((size_t)e*(4*Nz) + col0)*(size_t)KD;
    } else {
        Wbp = g_wouth + ((size_t)e*Dz + col0)*(size_t)KD;
    }

    extern __shared__ char smem[];
    int* s_tok = (int*)smem;
    const uint32_t sb = smem_u32(smem);
    const int t = threadIdx.x, wid = t >> 5, lid = t & 31;

    if (t < 128){
        int i = mt*128 + t;
        s_tok[t] = (i < cnt) ? g_tok[off + i] : -1;
    }
    __syncthreads();

    // ---- cp.async addressing: 64B rows, 4 segs of 16B; 2 rows each ----
    const int seg = t & 3;
    const int r0  = t >> 2;              // 0..63
    uint32_t dA[2]; uint32_t szA[2]; uint32_t iA[2];
    #pragma unroll
    for (int i = 0; i < 2; i++){
        int row = r0 + 64*i;             // 0..127 (token row)
        int tok = s_tok[row];
        dA[i]  = sw64((uint32_t)(row*64 + seg*16));
        szA[i] = (tok >= 0) ? 16u : 0u;
        iA[i]  = (uint32_t)(tok >= 0 ? tok : 0) * KD + seg*8;
    }
    uint32_t dB[2]; uint32_t iB[2];
    #pragma unroll
    for (int i = 0; i < 2; i++){
        int row = r0 + 64*i;             // 0..127 (output col)
        dB[i] = sw64((uint32_t)(row*64 + seg*16));
        iB[i] = (uint32_t)row * KD + seg*8;
    }

    auto stage_cp = [&](int k, uint32_t bufb){
        const uint32_t ko = (uint32_t)k*32;
        #pragma unroll
        for (int i = 0; i < 2; i++)
            CP16(bufb + dA[i], Ah + iA[i] + ko, szA[i]);
        #pragma unroll
        for (int i = 0; i < 2; i++)
            CP16(bufb + OFF_B + dB[i], Wbp + iB[i] + ko, 16u);
    };

    // ---- ldmatrix addressing (64B rows, SW64) ----
    const int wr = wid & 3, wc = wid >> 2;     // 4 M-strips x 2 N-strips
    const int lrow = lid & 15;
    const uint32_t kl = (uint32_t)((lid >> 4) * 16);  // k-half byte offset
    uint32_t aoff[2], axor[2], boff[4], bxor[4];
    #pragma unroll
    for (int m = 0; m < 2; m++){
        int row = wr*32 + m*16 + lrow;
        aoff[m] = (uint32_t)(row*64);
        axor[m] = (uint32_t)((row & 6) << 3);
    }
    #pragma unroll
    for (int nt = 0; nt < 4; nt++){
        int row = wc*64 + nt*16 + lrow;
        boff[nt] = (uint32_t)(row*64);
        bxor[nt] = (uint32_t)((row & 6) << 3);
    }

    float acc[2][8][4];
    #pragma unroll
    for (int m = 0; m < 2; m++)
        #pragma unroll
        for (int nb = 0; nb < 8; nb++)
            #pragma unroll
            for (int j = 0; j < 4; j++) acc[m][nb][j] = 0.f;

    const uint32_t bufs[3] = { sb + SM_BUF,
                               sb + SM_BUF + BUF_STRIDE,
                               sb + SM_BUF + 2*BUF_STRIDE };

    // prologue: fill 2 of 3 stages
    stage_cp(0, bufs[0]); CP_COMMIT();
    stage_cp(1, bufs[1]); CP_COMMIT();

    int bi = 0;
    for (int k = 0; k < NS; k++){
        if (k + 1 < NS) cp_wait<1>(); else cp_wait<0>();
        __syncthreads();
        if (k + 2 < NS){
            int b2 = bi + 2; if (b2 >= 3) b2 -= 3;
            stage_cp(k+2, bufs[b2]);
            CP_COMMIT();
        }
        const uint32_t bb = bufs[bi];
        #pragma unroll
        for (int ks = 0; ks < 2; ks++){
            const uint32_t kb = (uint32_t)(ks*32) + kl;
            uint32_t Abf[2][4];
            #pragma unroll
            for (int m = 0; m < 2; m++)
                LDSM4(Abf[m], bb + aoff[m] + (kb ^ axor[m]));
            #pragma unroll
            for (int hh = 0; hh < 2; hh++){
                uint32_t Bbf[2][4];
                #pragma unroll
                for (int j = 0; j < 2; j++){
                    const int nt = hh*2 + j;
                    LDSM4(Bbf[j], bb + OFF_B + boff[nt] + (kb ^ bxor[nt]));
                }
                #pragma unroll
                for (int m = 0; m < 2; m++)
                    #pragma unroll
                    for (int q = 0; q < 4; q++){
                        const int nb = hh*4 + q;
                        const int j = q >> 1, p = q & 1;
                        MMA(acc[m][nb], Abf[m], Bbf[j][p], Bbf[j][p+2]);
                    }
            }
        }
        if (++bi == 3) bi = 0;
    }
    __syncthreads();

    // ---- epilogue ----
    const int er = lid >> 2;
    const int ec = (lid & 3) * 2;
    const int cb0 = wc*64 + ec;   // base col within 128-wide tile (+nb*8)
    #pragma unroll
    for (int m = 0; m < 2; m++){
        #pragma unroll
        for (int h = 0; h < 2; h++){
            const int row = wr*32 + m*16 + h*8 + er;
            const int tok = s_tok[row];
            if (tok < 0) continue;
            float v[16];
            #pragma unroll
            for (int nb = 0; nb < 8; nb++){
                v[2*nb]   = acc[m][nb][2*h];
                v[2*nb+1] = acc[m][nb][2*h+1];
            }

            if (STAGE == 0){
                if (col0 < Nz){
                    float* dst = g_u + (size_t)tok*Nz + col0 + cb0;
                    #pragma unroll
                    for (int nb = 0; nb < 8; nb++)
                        *(float2*)(dst + nb*8) = make_float2(v[2*nb], v[2*nb+1]);
                } else {
                    const size_t base = (size_t)tok*Hz + (col0 - Nz) + cb0;
                    #pragma unroll
                    for (int nb = 0; nb < 8; nb++){
                        float s0 = v[2*nb]   * sig_fast(v[2*nb]);
                        float s1 = v[2*nb+1] * sig_fast(v[2*nb+1]);
                        *(uint*)(g_shh + base + nb*8) = hf2(s0, s1);
                    }
                }
            } else if (STAGE == 1){
                const int q  = col0 >> 8;
                const int n0 = (col0 & 255) + cb0;
                const size_t p = (size_t)tok*Nz + n0;
                if (q == 0){
                    #pragma unroll
                    for (int nb = 0; nb < 8; nb++)
                        *(float2*)(g_a + p + nb*8) =
                            make_float2(sig_fast(v[2*nb]), sig_fast(v[2*nb+1]));
                } else if (q == 1){
                    #pragma unroll
                    for (int nb = 0; nb < 8; nb++){
                        float2 u2 = *(const float2*)(g_u + p + nb*8);
                        *(float2*)(g_bu + p + nb*8) =
                            make_float2(tanh_fast(v[2*nb])*u2.x, tanh_fast(v[2*nb+1])*u2.y);
                    }
                } else if (q == 2){
                    #pragma unroll
                    for (int nb = 0; nb < 8; nb++)
                        *(float2*)(g_c + p + nb*8) =
                            make_float2(tanh_fast(v[2*nb]), tanh_fast(v[2*nb+1]));
                } else {
                    #pragma unroll
                    for (int nb = 0; nb < 8; nb++){
                        float2 u2 = *(const float2*)(g_u + p + nb*8);
                        float2 d2 = *(const float2*)(dpar + (size_t)e*Nz + n0 + nb*8);
                        *(float2*)(g_sk + p + nb*8) =
                            make_float2(d2.x*sig_fast(v[2*nb])*u2.x,
                                        d2.y*sig_fast(v[2*nb+1])*u2.y);
                    }
                }
            } else {
                float* dst = outp + (size_t)tok*Dz + col0 + cb0;
                #pragma unroll
                for (int nb = 0; nb < 8; nb++)
                    *(float2*)(dst + nb*8) = make_float2(v[2*nb], v[2*nb+1]);
            }
        }
    }
}

// ---------------- sequential scan: thread per (b,n) channel ------------------
struct Grp { float a[8], bu[8], c[8], sk[8]; int r[8]; };

__device__ __forceinline__ void load_grp(Grp& g, size_t base, int brow, int s0){
    #pragma unroll
    for (int i = 0; i < 8; i++){
        size_t p = base + (size_t)(s0 + i) * Nz;
        g.a[i]  = g_a [p];
        g.bu[i] = g_bu[p];
        g.c[i]  = g_c [p];
        g.sk[i] = g_sk[p];
        g.r[i]  = g_routes[brow + s0 + i];
    }
}
__device__ __forceinline__ void comp_grp(const Grp& g, size_t base, int s0, float h[Ez]){
    #pragma unroll
    for (int i = 0; i < 8; i++){
        int r = g.r[i];
        float hp = 0.f;
        #pragma unroll
        for (int e = 0; e < Ez; e++) if (r == e) hp = h[e];
        float hn = fmaf(g.a[i], hp, g.bu[i]);
        #pragma unroll
        for (int e = 0; e < Ez; e++) if (r == e) h[e] = hn;
        float yv = fmaf(g.c[i], hn, g.sk[i]);
        size_t p = base + (size_t)(s0 + i) * Nz;
        g_yh[p] = (ushort)(hf2(yv, yv) & 0xffffu);
    }
}
__global__ void k_scan(){
    const int b = blockIdx.x;
    const int n = blockIdx.y * 32 + threadIdx.x;
    const int brow = b * Sz;
    const size_t base = (size_t)brow * Nz + n;
    float h[Ez];
    #pragma unroll
    for (int e = 0; e < Ez; e++) h[e] = 0.f;

    Grp g0, g1;
    load_grp(g0, base, brow, 0);
    for (int s0 = 0; s0 < Sz; s0 += 16){
        load_grp(g1, base, brow, s0 + 8);
        comp_grp(g0, base, s0, h);
        if (s0 + 16 < Sz) load_grp(g0, base, brow, s0 + 16);
        comp_grp(g1, base, s0 + 8, h);
    }
}

// ---------------- launch ------------------------------------------------------
extern "C" void kernel_launch(void* const* d_in, const int* in_sizes, int n_in,
                              void* d_out, int out_size){
    const float* x     = (const float*)d_in[0];
    const int*   tid   = (const int*)  d_in[1];
    const float* Win   = (const float*)d_in[2];
    const float* Wsin  = (const float*)d_in[3];
    const float* Wsout = (const float*)d_in[4];
    const float* Wout  = (const float*)d_in[5];
    const float* dpar  = (const float*)d_in[6];
    float* out = (float*)d_out;

    cudaFuncSetAttribute((const void*)k_gemm<0>, cudaFuncAttributeMaxDynamicSharedMemorySize, SMEM_BYTES);
    cudaFuncSetAttribute((const void*)k_gemm<1>, cudaFuncAttributeMaxDynamicSharedMemorySize, SMEM_BYTES);
    cudaFuncSetAttribute((const void*)k_gemm<2>, cudaFuncAttributeMaxDynamicSharedMemorySize, SMEM_BYTES);

    k_zero     <<<1, 32>>>();                          // 0
    k_route    <<<Tz/256, 256>>>(tid);                 // 1
    k_off      <<<1, 1>>>();                           // 2
    k_scatter  <<<Tz/256, 256>>>();                    // 3
    k_split_all<<<2048, 256>>>(x, Win, Wsin, Wsout, Wout); // 4

    // stage 0: fused in_proj + selector_in (768 cols), K = 1024   -- launch 5
    k_gemm<0><<<dim3(768/128,  Tz/128, Ez), 256, SMEM_BYTES>>>(dpar, nullptr);
    // stage 1: selector_out (1024 cols), K = 512, fused activations
    k_gemm<1><<<dim3(1024/128, Tz/128, Ez), 256, SMEM_BYTES>>>(dpar, nullptr);
    // sequential SSM scan (writes fp16 y)
    k_scan   <<<dim3(Bz, Nz/32), 32>>>();
    // stage 2: out_proj (1024 cols), K = 256
    k_gemm<2><<<dim3(1024/128, Tz/128, Ez), 256, SMEM_BYTES>>>(dpar, out);
}

// round 16
// speedup vs baseline: 1.0049x; 1.0049x over previous
#include <cuda_runtime.h>
#include <cuda_fp16.h>
#include <cstdint>
#include <math.h>

#define Bz 8
#define Sz 2048
#define Dz 1024
#define Nz 256
#define Hz 512
#define Ez 8
#define Tz (Bz*Sz)   // 16384 tokens

typedef unsigned int uint;
typedef unsigned short ushort;

// ---------------- scratch (static device allocations, allowed) -------------
__device__ int   g_routes[Tz];
__device__ int   g_cnt[Ez];
__device__ int   g_off[Ez+1];
__device__ int   g_cur[Ez];
__device__ int   g_tok[Tz];

__device__ float g_u [(size_t)Tz*Nz];
__device__ float g_a [(size_t)Tz*Nz];
__device__ float g_bu[(size_t)Tz*Nz];
__device__ float g_c [(size_t)Tz*Nz];
__device__ float g_sk[(size_t)Tz*Nz];

// fp16 operand buffers (single-rounded activations AND weights)
__device__ ushort g_xh [(size_t)Tz*Dz];
__device__ ushort g_shh[(size_t)Tz*Hz];
__device__ ushort g_yh [(size_t)Tz*Nz];
__device__ ushort g_winh [(size_t)Ez*Nz*Dz];
__device__ ushort g_wsinh[(size_t)Ez*Hz*Dz];
__device__ ushort g_wsouth[(size_t)Ez*4*Nz*Hz];
__device__ ushort g_wouth[(size_t)Ez*Dz*Nz];

// ---------------- helpers ----------------------------------------------------
__device__ __forceinline__ uint32_t smem_u32(const void* p){
    uint32_t a;
    asm("{ .reg .u64 t; cvta.to.shared.u64 t, %1; cvt.u32.u64 %0, t; }" : "=r"(a) : "l"(p));
    return a;
}
__device__ __forceinline__ float tanh_fast(float x){
    float r; asm("tanh.approx.f32 %0, %1;" : "=f"(r) : "f"(x)); return r;
}
__device__ __forceinline__ float sig_fast(float x){ return fmaf(0.5f, tanh_fast(0.5f*x), 0.5f); }

// pack two floats into f16x2 (lo in low half)
__device__ __forceinline__ uint hf2(float lo, float hi){
    uint r; asm("cvt.rn.f16x2.f32 %0, %1, %2;" : "=r"(r) : "f"(hi), "f"(lo)); return r;
}
// SW64 swizzle for 64-byte SMEM rows (conflict-free ldmatrix with BK=32 fp16)
__device__ __forceinline__ uint32_t sw64(uint32_t o){ return o ^ ((o>>3)&0x30); }

#define CP16(dst, src, sz) \
    asm volatile("cp.async.cg.shared.global [%0], [%1], 16, %2;" \
                 :: "r"(dst), "l"(src), "r"(sz) : "memory")
#define CP_COMMIT() asm volatile("cp.async.commit_group;" ::: "memory")
template<int N> __device__ __forceinline__ void cp_wait(){
    asm volatile("cp.async.wait_group %0;" :: "n"(N) : "memory");
}
#define LDSM4(r, addr) \
    asm volatile("ldmatrix.sync.aligned.m8n8.x4.shared.b16 {%0,%1,%2,%3}, [%4];" \
                 : "=r"((r)[0]),"=r"((r)[1]),"=r"((r)[2]),"=r"((r)[3]) : "r"(addr))
#define MMA(d, a, b0_, b1_) \
    asm volatile("mma.sync.aligned.m16n8k16.row.col.f32.f16.f16.f32 " \
                 "{%0,%1,%2,%3},{%4,%5,%6,%7},{%8,%9},{%0,%1,%2,%3};" \
                 : "+f"((d)[0]),"+f"((d)[1]),"+f"((d)[2]),"+f"((d)[3]) \
                 : "r"((a)[0]),"r"((a)[1]),"r"((a)[2]),"r"((a)[3]), "r"(b0_),"r"(b1_))

// ---------------- fused fp32 -> fp16 conversion (ALL tensors) -----------------
__device__ __forceinline__ void cvt_h(const float4* __restrict__ s,
                                      uint2* __restrict__ dh, size_t i){
    float4 v = s[i];
    uint2 o; o.x = hf2(v.x, v.y); o.y = hf2(v.z, v.w);
    dh[i] = o;
}

__global__ void k_split_all(const float* __restrict__ x,   const float* __restrict__ Win,
                            const float* __restrict__ Wsin, const float* __restrict__ Wsout,
                            const float* __restrict__ Wout){
    constexpr size_t c0 = (size_t)Tz*Dz/4;                 // x
    constexpr size_t c1 = c0 + (size_t)Ez*Nz*Dz/4;         // + win
    constexpr size_t c2 = c1 + (size_t)Ez*Hz*Dz/4;         // + wsin
    constexpr size_t c3 = c2 + (size_t)Ez*4*Nz*Hz/4;       // + wsout
    constexpr size_t c4 = c3 + (size_t)Ez*Dz*Nz/4;         // + wout
    size_t i = (size_t)blockIdx.x*blockDim.x + threadIdx.x;
    size_t stride = (size_t)gridDim.x*blockDim.x;
    for (; i < c4; i += stride){
        if (i < c0)      cvt_h((const float4*)x,     (uint2*)g_xh,     i);
        else if (i < c1) cvt_h((const float4*)Win,   (uint2*)g_winh,   i - c0);
        else if (i < c2) cvt_h((const float4*)Wsin,  (uint2*)g_wsinh,  i - c1);
        else if (i < c3) cvt_h((const float4*)Wsout, (uint2*)g_wsouth, i - c2);
        else             cvt_h((const float4*)Wout,  (uint2*)g_wouth,  i - c3);
    }
}

// ---------------- routing / counting sort ------------------------------------
__global__ void k_zero(){
    int t = threadIdx.x;
    if (t < Ez){ g_cnt[t] = 0; g_cur[t] = 0; }
}
__global__ void k_route(const int* __restrict__ tid){
    int t = blockIdx.x*256 + threadIdx.x;
    if (t >= Tz) return;
    unsigned x = (unsigned)tid[t];
    x ^= x >> 16; x *= 2246822507u;
    x ^= x >> 13; x *= 3266489909u;
    x ^= x >> 16;
    int r = (int)(x & (unsigned)(Ez-1));
    g_routes[t] = r;
    atomicAdd(&g_cnt[r], 1);
}
__global__ void k_off(){
    int s = 0;
    for (int e = 0; e < Ez; e++){ g_off[e] = s; s += g_cnt[e]; }
    g_off[Ez] = s;
}
__global__ void k_scatter(){
    int t = blockIdx.x*256 + threadIdx.x;
    if (t >= Tz) return;
    int r = g_routes[t];
    int pos = g_off[r] + atomicAdd(&g_cur[r], 1);
    g_tok[pos] = t;
}

// ---------------- HMMA grouped GEMM ------------------------------------------
// CTA tile: 128 tokens x 128 cols, BK=32, 8 warps (4x2), warp tile 32x64.
// Single-pass fp16, fp32 accumulate. 3-stage cp.async pipeline (wait_group 1).
// Per stage: A 8K | B 8K = 16KB; 3 stages + 1K header = 50176 B; occupancy 2.
#define SM_BUF     1024
#define OFF_B      8192
#define BUF_STRIDE 16384
#define SMEM_BYTES (SM_BUF + 3*BUF_STRIDE)

template<int STAGE>
__global__ void __launch_bounds__(256,2)
k_gemm(const float* __restrict__ dpar, float* __restrict__ outp)
{
    constexpr int KD = (STAGE==0) ? Dz : (STAGE==1) ? Hz : Nz;
    constexpr int NS = KD / 32;

    const int e   = blockIdx.z;
    const int cnt = g_cnt[e];
    const int mt  = blockIdx.y;
    if (mt*128 >= cnt) return;
    const int off  = g_off[e];
    const int col0 = blockIdx.x * 128;

    const ushort* Ah = (STAGE==0) ? g_xh : (STAGE==1) ? g_shh : g_yh;
    const ushort* Wbp;
    if (STAGE==0){
        Wbp = (col0 < Nz) ? (g_winh + ((size_t)e*Nz + col0)*(size_t)KD)
                          : (g_wsinh + ((size_t)e*Hz + (col0-Nz))*(size_t)KD);
    } else if (STAGE==1){
        Wbp = g_wsouth + ((size_t)e*(4*Nz) + col0)*(size_t)KD;
    } else {
        Wbp = g_wouth + ((size_t)e*Dz + col0)*(size_t)KD;
    }

    extern __shared__ char smem[];
    int* s_tok = (int*)smem;
    const uint32_t sb = smem_u32(smem);
    const int t = threadIdx.x, wid = t >> 5, lid = t & 31;

    if (t < 128){
        int i = mt*128 + t;
        s_tok[t] = (i < cnt) ? g_tok[off + i] : -1;
    }
    __syncthreads();

    // ---- cp.async addressing: 64B rows, 4 segs of 16B; 2 rows each ----
    const int seg = t & 3;
    const int r0  = t >> 2;              // 0..63
    uint32_t dA[2]; uint32_t szA[2]; uint32_t iA[2];
    #pragma unroll
    for (int i = 0; i < 2; i++){
        int row = r0 + 64*i;             // 0..127 (token row)
        int tok = s_tok[row];
        dA[i]  = sw64((uint32_t)(row*64 + seg*16));
        szA[i] = (tok >= 0) ? 16u : 0u;
        iA[i]  = (uint32_t)(tok >= 0 ? tok : 0) * KD + seg*8;
    }
    uint32_t dB[2]; uint32_t iB[2];
    #pragma unroll
    for (int i = 0; i < 2; i++){
        int row = r0 + 64*i;             // 0..127 (output col)
        dB[i] = sw64((uint32_t)(row*64 + seg*16));
        iB[i] = (uint32_t)row * KD + seg*8;
    }

    auto stage_cp = [&](int k, uint32_t bufb){
        const uint32_t ko = (uint32_t)k*32;
        #pragma unroll
        for (int i = 0; i < 2; i++)
            CP16(bufb + dA[i], Ah + iA[i] + ko, szA[i]);
        #pragma unroll
        for (int i = 0; i < 2; i++)
            CP16(bufb + OFF_B + dB[i], Wbp + iB[i] + ko, 16u);
    };

    // ---- ldmatrix addressing (64B rows, SW64) ----
    const int wr = wid & 3, wc = wid >> 2;     // 4 M-strips x 2 N-strips
    const int lrow = lid & 15;
    const uint32_t kl = (uint32_t)((lid >> 4) * 16);  // k-half byte offset
    uint32_t aoff[2], axor[2], boff[4], bxor[4];
    #pragma unroll
    for (int m = 0; m < 2; m++){
        int row = wr*32 + m*16 + lrow;
        aoff[m] = (uint32_t)(row*64);
        axor[m] = (uint32_t)((row & 6) << 3);
    }
    #pragma unroll
    for (int nt = 0; nt < 4; nt++){
        int row = wc*64 + nt*16 + lrow;
        boff[nt] = (uint32_t)(row*64);
        bxor[nt] = (uint32_t)((row & 6) << 3);
    }

    float acc[2][8][4];
    #pragma unroll
    for (int m = 0; m < 2; m++)
        #pragma unroll
        for (int nb = 0; nb < 8; nb++)
            #pragma unroll
            for (int j = 0; j < 4; j++) acc[m][nb][j] = 0.f;

    const uint32_t bufs[3] = { sb + SM_BUF,
                               sb + SM_BUF + BUF_STRIDE,
                               sb + SM_BUF + 2*BUF_STRIDE };

    // prologue: fill 2 of 3 stages
    stage_cp(0, bufs[0]); CP_COMMIT();
    stage_cp(1, bufs[1]); CP_COMMIT();

    int bi = 0;
    for (int k = 0; k < NS; k++){
        if (k + 1 < NS) cp_wait<1>(); else cp_wait<0>();
        __syncthreads();
        if (k + 2 < NS){
            int b2 = bi + 2; if (b2 >= 3) b2 -= 3;
            stage_cp(k+2, bufs[b2]);
            CP_COMMIT();
        }
        const uint32_t bb = bufs[bi];
        #pragma unroll
        for (int ks = 0; ks < 2; ks++){
            const uint32_t kb = (uint32_t)(ks*32) + kl;
            uint32_t Abf[2][4];
            #pragma unroll
            for (int m = 0; m < 2; m++)
                LDSM4(Abf[m], bb + aoff[m] + (kb ^ axor[m]));
            #pragma unroll
            for (int hh = 0; hh < 2; hh++){
                uint32_t Bbf[2][4];
                #pragma unroll
                for (int j = 0; j < 2; j++){
                    const int nt = hh*2 + j;
                    LDSM4(Bbf[j], bb + OFF_B + boff[nt] + (kb ^ bxor[nt]));
                }
                #pragma unroll
                for (int m = 0; m < 2; m++)
                    #pragma unroll
                    for (int q = 0; q < 4; q++){
                        const int nb = hh*4 + q;
                        const int j = q >> 1, p = q & 1;
                        MMA(acc[m][nb], Abf[m], Bbf[j][p], Bbf[j][p+2]);
                    }
            }
        }
        if (++bi == 3) bi = 0;
    }
    __syncthreads();

    // ---- epilogue ----
    const int er = lid >> 2;
    const int ec = (lid & 3) * 2;
    const int cb0 = wc*64 + ec;   // base col within 128-wide tile (+nb*8)
    #pragma unroll
    for (int m = 0; m < 2; m++){
        #pragma unroll
        for (int h = 0; h < 2; h++){
            const int row = wr*32 + m*16 + h*8 + er;
            const int tok = s_tok[row];
            if (tok < 0) continue;
            float v[16];
            #pragma unroll
            for (int nb = 0; nb < 8; nb++){
                v[2*nb]   = acc[m][nb][2*h];
                v[2*nb+1] = acc[m][nb][2*h+1];
            }

            if (STAGE == 0){
                if (col0 < Nz){
                    float* dst = g_u + (size_t)tok*Nz + col0 + cb0;
                    #pragma unroll
                    for (int nb = 0; nb < 8; nb++)
                        *(float2*)(dst + nb*8) = make_float2(v[2*nb], v[2*nb+1]);
                } else {
                    const size_t base = (size_t)tok*Hz + (col0 - Nz) + cb0;
                    #pragma unroll
                    for (int nb = 0; nb < 8; nb++){
                        float s0 = v[2*nb]   * sig_fast(v[2*nb]);
                        float s1 = v[2*nb+1] * sig_fast(v[2*nb+1]);
                        *(uint*)(g_shh + base + nb*8) = hf2(s0, s1);
                    }
                }
            } else if (STAGE == 1){
                const int q  = col0 >> 8;
                const int n0 = (col0 & 255) + cb0;
                const size_t p = (size_t)tok*Nz + n0;
                if (q == 0){
                    #pragma unroll
                    for (int nb = 0; nb < 8; nb++)
                        *(float2*)(g_a + p + nb*8) =
                            make_float2(sig_fast(v[2*nb]), sig_fast(v[2*nb+1]));
                } else if (q == 1){
                    #pragma unroll
                    for (int nb = 0; nb < 8; nb++){
                        float2 u2 = *(const float2*)(g_u + p + nb*8);
                        *(float2*)(g_bu + p + nb*8) =
                            make_float2(tanh_fast(v[2*nb])*u2.x, tanh_fast(v[2*nb+1])*u2.y);
                    }
                } else if (q == 2){
                    #pragma unroll
                    for (int nb = 0; nb < 8; nb++)
                        *(float2*)(g_c + p + nb*8) =
                            make_float2(tanh_fast(v[2*nb]), tanh_fast(v[2*nb+1]));
                } else {
                    #pragma unroll
                    for (int nb = 0; nb < 8; nb++){
                        float2 u2 = *(const float2*)(g_u + p + nb*8);
                        float2 d2 = *(const float2*)(dpar + (size_t)e*Nz + n0 + nb*8);
                        *(float2*)(g_sk + p + nb*8) =
                            make_float2(d2.x*sig_fast(v[2*nb])*u2.x,
                                        d2.y*sig_fast(v[2*nb+1])*u2.y);
                    }
                }
            } else {
                float* dst = outp + (size_t)tok*Dz + col0 + cb0;
                #pragma unroll
                for (int nb = 0; nb < 8; nb++)
                    *(float2*)(dst + nb*8) = make_float2(v[2*nb], v[2*nb+1]);
            }
        }
    }
}

// ---------------- sequential scan: thread per (b,n) channel ------------------
struct Grp { float a[8], bu[8], c[8], sk[8]; int r[8]; };

__device__ __forceinline__ void load_grp(Grp& g, size_t base, int brow, int s0){
    #pragma unroll
    for (int i = 0; i < 8; i++){
        size_t p = base + (size_t)(s0 + i) * Nz;
        g.a[i]  = g_a [p];
        g.bu[i] = g_bu[p];
        g.c[i]  = g_c [p];
        g.sk[i] = g_sk[p];
        g.r[i]  = g_routes[brow + s0 + i];
    }
}
__device__ __forceinline__ void comp_grp(const Grp& g, size_t base, int s0, float h[Ez]){
    #pragma unroll
    for (int i = 0; i < 8; i++){
        int r = g.r[i];
        float hp = 0.f;
        #pragma unroll
        for (int e = 0; e < Ez; e++) if (r == e) hp = h[e];
        float hn = fmaf(g.a[i], hp, g.bu[i]);
        #pragma unroll
        for (int e = 0; e < Ez; e++) if (r == e) h[e] = hn;
        float yv = fmaf(g.c[i], hn, g.sk[i]);
        size_t p = base + (size_t)(s0 + i) * Nz;
        g_yh[p] = (ushort)(hf2(yv, yv) & 0xffffu);
    }
}
__global__ void k_scan(){
    const int b = blockIdx.x;
    const int n = blockIdx.y * 32 + threadIdx.x;
    const int brow = b * Sz;
    const size_t base = (size_t)brow * Nz + n;
    float h[Ez];
    #pragma unroll
    for (int e = 0; e < Ez; e++) h[e] = 0.f;

    Grp g0, g1;
    load_grp(g0, base, brow, 0);
    for (int s0 = 0; s0 < Sz; s0 += 16){
        load_grp(g1, base, brow, s0 + 8);
        comp_grp(g0, base, s0, h);
        if (s0 + 16 < Sz) load_grp(g0, base, brow, s0 + 16);
        comp_grp(g1, base, s0 + 8, h);
    }
}

// ---------------- launch ------------------------------------------------------
extern "C" void kernel_launch(void* const* d_in, const int* in_sizes, int n_in,
                              void* d_out, int out_size){
    const float* x     = (const float*)d_in[0];
    const int*   tid   = (const int*)  d_in[1];
    const float* Win   = (const float*)d_in[2];
    const float* Wsin  = (const float*)d_in[3];
    const float* Wsout = (const float*)d_in[4];
    const float* Wout  = (const float*)d_in[5];
    const float* dpar  = (const float*)d_in[6];
    float* out = (float*)d_out;

    cudaFuncSetAttribute((const void*)k_gemm<0>, cudaFuncAttributeMaxDynamicSharedMemorySize, SMEM_BYTES);
    cudaFuncSetAttribute((const void*)k_gemm<1>, cudaFuncAttributeMaxDynamicSharedMemorySize, SMEM_BYTES);
    cudaFuncSetAttribute((const void*)k_gemm<2>, cudaFuncAttributeMaxDynamicSharedMemorySize, SMEM_BYTES);

    k_zero     <<<1, 32>>>();                          // 0
    k_route    <<<Tz/256, 256>>>(tid);                 // 1
    k_off      <<<1, 1>>>();                           // 2
    k_scatter  <<<Tz/256, 256>>>();                    // 3
    k_split_all<<<2048, 256>>>(x, Win, Wsin, Wsout, Wout); // 4

    // stage 0: fused in_proj + selector_in (768 cols), K = 1024   -- launch 5
    k_gemm<0><<<dim3(768/128,  Tz/128, Ez), 256, SMEM_BYTES>>>(dpar, nullptr);
    // stage 1: selector_out (1024 cols), K = 512, fused activations
    k_gemm<1><<<dim3(1024/128, Tz/128, Ez), 256, SMEM_BYTES>>>(dpar, nullptr);
    // sequential SSM scan (writes fp16 y)
    k_scan   <<<dim3(Bz, Nz/32), 32>>>();
    // stage 2: out_proj (1024 cols), K = 256
    k_gemm<2><<<dim3(1024/128, Tz/128, Ez), 256, SMEM_BYTES>>>(dpar, out);
}